// round 2
// baseline (speedup 1.0000x reference)
#include <cuda_runtime.h>

#define H        128
#define NROWS    200000
#define M_NODES  1000
#define J_NODES  5000
#define RPW      16                 // rows per warp per pass over W1
#define SBLOCKS  148                // 1 block/SM (192KB smem)
#define SWARPS   8                  // warps per score block
#define NWTOT    (SBLOCKS * SWARPS) // 1184 warp partials
#define JB       8                  // jobs per precompute block

typedef unsigned long long u64;

// ---------------- device scratch ----------------
__device__ __align__(16) float g_c[H];
__device__ __align__(16) float g_A[M_NODES * H];
__device__ __align__(16) float g_B[J_NODES * H];
__device__ float g_wmax[NWTOT];
__device__ int   g_warg[NWTOT];
__device__ float g_wZ[NWTOT];
__device__ float g_wS1[NWTOT];

// ---------------- packed f32x2 helpers ----------------
__device__ __forceinline__ u64 ffma2(u64 a, u64 b, u64 c) {
    u64 d;
    asm("fma.rn.f32x2 %0, %1, %2, %3;" : "=l"(d) : "l"(a), "l"(b), "l"(c));
    return d;
}
__device__ __forceinline__ u64 dup2(float x) {
    u64 d;
    asm("mov.b64 %0, {%1, %1};" : "=l"(d) : "r"(__float_as_uint(x)));
    return d;
}
__device__ __forceinline__ float2 unpack2(u64 v) {
    float2 r;
    asm("mov.b64 {%0, %1}, %2;" : "=f"(r.x), "=f"(r.y) : "l"(v));
    return r;
}

// ---------------- K1: precompute cg, A, B (tiled: 8 rows/block) ----------------
// grid = 125 + 625 + 1 = 751 blocks of 128 threads.
__global__ void precompute_kernel(const float* __restrict__ xg,
                                  const float* __restrict__ xm,
                                  const float* __restrict__ xj,
                                  const float* __restrict__ W0,
                                  const float* __restrict__ b0) {
    int b = blockIdx.x;
    int t = threadIdx.x;
    __shared__ float xs[JB][H];

    if (b < M_NODES / JB) {
        int m0 = b * JB;
        #pragma unroll
        for (int jj = 0; jj < JB; jj++) xs[jj][t] = xm[(m0 + jj) * H + t];
        __syncthreads();
        float acc[JB];
        #pragma unroll
        for (int jj = 0; jj < JB; jj++) acc[jj] = 0.f;
        const float* w = W0 + (2 * H) * H + t;
        #pragma unroll 4
        for (int i = 0; i < H; i++) {
            float wv = w[i * H];
            #pragma unroll
            for (int jj = 0; jj < JB; jj++) acc[jj] += xs[jj][i] * wv;
        }
        #pragma unroll
        for (int jj = 0; jj < JB; jj++) g_A[(m0 + jj) * H + t] = acc[jj];
    } else if (b < M_NODES / JB + J_NODES / JB) {
        int j0 = (b - M_NODES / JB) * JB;
        #pragma unroll
        for (int jj = 0; jj < JB; jj++) xs[jj][t] = xj[(j0 + jj) * H + t];
        __syncthreads();
        float acc[JB];
        #pragma unroll
        for (int jj = 0; jj < JB; jj++) acc[jj] = 0.f;
        const float* w = W0 + (3 * H) * H + t;
        #pragma unroll 4
        for (int i = 0; i < H; i++) {
            float wv = w[i * H];
            #pragma unroll
            for (int jj = 0; jj < JB; jj++) acc[jj] += xs[jj][i] * wv;
        }
        #pragma unroll
        for (int jj = 0; jj < JB; jj++) g_B[(j0 + jj) * H + t] = acc[jj];
    } else {
        // graph constant: c = x_graph @ W0[0:2H] + b0
        __shared__ float x2[2 * H];
        x2[t] = xg[t];
        x2[t + H] = xg[t + H];
        __syncthreads();
        float acc = b0[t];
        const float* w = W0 + t;
        #pragma unroll 8
        for (int i = 0; i < 2 * H; i++) acc += x2[i] * w[i * H];
        g_c[t] = acc;
    }
}

// ---------------- K2: fused score + online softmax ----------------
// W1 in smem (64KB) + per-warp duplicated-h staging (128KB). Layer-2 runs on
// packed fma.rn.f32x2: weights packed across adjacent output columns (free —
// contiguous in smem), h pre-duplicated (h,h) at staging time. Each warp keeps
// a full online-softmax state (max/arg/Z/S1), written as one partial per warp.
__global__ void __launch_bounds__(256, 1) score_kernel(
        const int*   __restrict__ m_ids,
        const int*   __restrict__ job_idx,
        const float* __restrict__ W1,
        const float* __restrict__ b1,
        const float* __restrict__ W2,
        const float* __restrict__ b2) {
    extern __shared__ float smem[];
    float* W1s = smem;                       // H*H floats = 64KB
    u64*   hdup = (u64*)(smem + H * H);      // SWARPS * RPW * H u64 = 128KB

    int tid  = threadIdx.x;
    int lane = tid & 31;
    int wid  = tid >> 5;

    for (int i = tid; i < H * H / 4; i += 256)
        ((float4*)W1s)[i] = ((const float4*)W1)[i];

    float4 creg  = ((const float4*)g_c)[lane];
    u64    b1p0  = ((const u64*)b1)[2 * lane];
    u64    b1p1  = ((const u64*)b1)[2 * lane + 1];
    float4 w2reg = ((const float4*)W2)[lane];
    float  b2v   = b2[0];
    __syncthreads();

    u64* myh = hdup + wid * (RPW * H);
    const float4* A4 = (const float4*)g_A;
    const float4* B4 = (const float4*)g_B;

    // online softmax state (kept uniform across all lanes of the warp)
    float mx = -3.402823466e38f, Z = 0.f, S1 = 0.f;
    int   arg = 0x7fffffff;

    int gw = blockIdx.x * SWARPS + wid;
    const int stride = SBLOCKS * SWARPS * RPW;

    for (int base = gw * RPW; base + RPW <= NROWS; base += stride) {
        // ---- build duplicated h0 for RPW rows ----
        #pragma unroll
        for (int r = 0; r < RPW; r++) {
            int m = m_ids[base + r];
            int j = job_idx[base + r];
            float4 a  = A4[m * (H / 4) + lane];
            float4 bb = B4[j * (H / 4) + lane];
            float h0 = fmaxf(creg.x + a.x + bb.x, 0.f);
            float h1 = fmaxf(creg.y + a.y + bb.y, 0.f);
            float h2 = fmaxf(creg.z + a.z + bb.z, 0.f);
            float h3 = fmaxf(creg.w + a.w + bb.w, 0.f);
            ulonglong2* dst = (ulonglong2*)(myh + r * H + 4 * lane);
            dst[0] = make_ulonglong2(dup2(h0), dup2(h1));
            dst[1] = make_ulonglong2(dup2(h2), dup2(h3));
        }
        __syncwarp();

        // ---- layer 2 on f32x2: acc pairs are (col 4l,4l+1) and (4l+2,4l+3) ----
        u64 acc[RPW][2];
        #pragma unroll
        for (int r = 0; r < RPW; r++) { acc[r][0] = b1p0; acc[r][1] = b1p1; }

        #pragma unroll 2
        for (int i4 = 0; i4 < H / 4; i4++) {
            ulonglong2 w0 = *(const ulonglong2*)(W1s + (4 * i4 + 0) * H + 4 * lane);
            ulonglong2 w1 = *(const ulonglong2*)(W1s + (4 * i4 + 1) * H + 4 * lane);
            ulonglong2 w2 = *(const ulonglong2*)(W1s + (4 * i4 + 2) * H + 4 * lane);
            ulonglong2 w3 = *(const ulonglong2*)(W1s + (4 * i4 + 3) * H + 4 * lane);
            #pragma unroll
            for (int r = 0; r < RPW; r++) {
                ulonglong2 ha = *(const ulonglong2*)(myh + r * H + 4 * i4);
                ulonglong2 hb = *(const ulonglong2*)(myh + r * H + 4 * i4 + 2);
                acc[r][0] = ffma2(ha.x, w0.x, acc[r][0]);
                acc[r][1] = ffma2(ha.x, w0.y, acc[r][1]);
                acc[r][0] = ffma2(ha.y, w1.x, acc[r][0]);
                acc[r][1] = ffma2(ha.y, w1.y, acc[r][1]);
                acc[r][0] = ffma2(hb.x, w2.x, acc[r][0]);
                acc[r][1] = ffma2(hb.x, w2.y, acc[r][1]);
                acc[r][0] = ffma2(hb.y, w3.x, acc[r][0]);
                acc[r][1] = ffma2(hb.y, w3.y, acc[r][1]);
            }
        }

        // ---- layer 3 + warp reduce + online softmax update ----
        #pragma unroll
        for (int r = 0; r < RPW; r++) {
            float2 a0 = unpack2(acc[r][0]);
            float2 a1 = unpack2(acc[r][1]);
            float s = fmaxf(a0.x, 0.f) * w2reg.x + fmaxf(a0.y, 0.f) * w2reg.y
                    + fmaxf(a1.x, 0.f) * w2reg.z + fmaxf(a1.y, 0.f) * w2reg.w;
            #pragma unroll
            for (int off = 16; off; off >>= 1)
                s += __shfl_xor_sync(0xffffffffu, s, off);
            s += b2v;
            // rows within a warp processed in increasing index -> '>' keeps first max
            if (s > mx) {
                float d = fmaxf(mx - s, -87.f);
                float e = expf(d);
                S1 = e * (S1 + d * Z);
                Z  = e * Z + 1.f;
                mx = s;
                arg = base + r;
            } else {
                float t = fmaxf(s - mx, -87.f);
                float e = expf(t);
                Z  += e;
                S1 += t * e;
            }
        }
        __syncwarp();
    }

    if (lane == 0) {
        g_wmax[gw] = mx;
        g_warg[gw] = arg;
        g_wZ[gw]   = Z;
        g_wS1[gw]  = S1;
    }
}

// ---------------- K3: merge 1184 warp partials, write outputs ----------------
__global__ void finalize_kernel(float* __restrict__ out) {
    __shared__ float smx[256], sZ[256], sS1[256];
    __shared__ int   sarg[256];
    int tid = threadIdx.x;

    float mx = -3.402823466e38f, Z = 0.f, S1 = 0.f;
    int   arg = 0x7fffffff;

    for (int i = tid; i < NWTOT; i += 256) {
        float qm = g_wmax[i], qZ = g_wZ[i], qS = g_wS1[i];
        int   qa = g_warg[i];
        if (qm > mx || (qm == mx && qa < arg)) {
            float d = fmaxf(mx - qm, -87.f);
            float e = expf(d);
            float Zo = Z, S1o = S1;
            Z  = qZ + e * Zo;
            S1 = qS + e * (S1o + d * Zo);
            mx = qm; arg = qa;
        } else {
            float d = fmaxf(qm - mx, -87.f);
            float e = expf(d);
            Z  += e * qZ;
            S1 += e * (qS + d * qZ);
        }
    }
    smx[tid] = mx; sarg[tid] = arg; sZ[tid] = Z; sS1[tid] = S1;
    __syncthreads();

    for (int s = 128; s; s >>= 1) {
        if (tid < s) {
            float qm = smx[tid + s], qZ = sZ[tid + s], qS = sS1[tid + s];
            int   qa = sarg[tid + s];
            if (qm > smx[tid] || (qm == smx[tid] && qa < sarg[tid])) {
                float d = fmaxf(smx[tid] - qm, -87.f);
                float e = expf(d);
                float Zo = sZ[tid], S1o = sS1[tid];
                sZ[tid]  = qZ + e * Zo;
                sS1[tid] = qS + e * (S1o + d * Zo);
                smx[tid] = qm; sarg[tid] = qa;
            } else {
                float d = fmaxf(qm - smx[tid], -87.f);
                float e = expf(d);
                sZ[tid]  += e * qZ;
                sS1[tid] += e * (qS + d * qZ);
            }
        }
        __syncthreads();
    }

    if (tid == 0) {
        float Zf   = sZ[0];
        float S1f  = sS1[0];
        float logZ = logf(Zf);
        out[0] = (float)sarg[0];
        out[1] = 1.0f / Zf;          // p[idx]   (t=0 at argmax)
        out[2] = -logZ;              // logp[idx]
        out[3] = logZ - S1f / Zf;    // entropy
    }
}

// ---------------- launch ----------------
extern "C" void kernel_launch(void* const* d_in, const int* in_sizes, int n_in,
                              void* d_out, int out_size) {
    const float* x_graph = (const float*)d_in[0];
    const float* x_m     = (const float*)d_in[1];
    const float* x_job   = (const float*)d_in[2];
    const int*   m_ids   = (const int*)  d_in[3];
    const int*   job_idx = (const int*)  d_in[4];
    const float* W0      = (const float*)d_in[5];
    const float* b0      = (const float*)d_in[6];
    const float* W1      = (const float*)d_in[7];
    const float* b1      = (const float*)d_in[8];
    const float* W2      = (const float*)d_in[9];
    const float* b2      = (const float*)d_in[10];
    float* out = (float*)d_out;

    const int smem_bytes = H * H * (int)sizeof(float)
                         + SWARPS * RPW * H * (int)sizeof(u64);   // 192KB
    cudaFuncSetAttribute(score_kernel,
                         cudaFuncAttributeMaxDynamicSharedMemorySize, smem_bytes);

    precompute_kernel<<<M_NODES / JB + J_NODES / JB + 1, H>>>(x_graph, x_m, x_job, W0, b0);
    score_kernel<<<SBLOCKS, 256, smem_bytes>>>(m_ids, job_idx, W1, b1, W2, b2);
    finalize_kernel<<<1, 256>>>(out);
}

// round 3
// speedup vs baseline: 1.0889x; 1.0889x over previous
#include <cuda_runtime.h>

#define H        128
#define NROWS    200000
#define M_NODES  1000
#define J_NODES  5000
#define RPW      8                  // rows per warp per pass over W1
#define SBLOCKS  148                // 1 block/SM
#define SWARPS   16                 // warps per score block (512 threads)
#define NWTOT    (SBLOCKS * SWARPS) // 2368 warp partials
#define JB       16                 // rows per precompute block

typedef unsigned long long u64;

// ---------------- device scratch ----------------
__device__ __align__(16) float g_c[H];
__device__ __align__(16) float g_A[M_NODES * H];
__device__ __align__(16) float g_B[J_NODES * H];
__device__ float g_wmax[NWTOT];
__device__ int   g_warg[NWTOT];
__device__ float g_wZ[NWTOT];
__device__ float g_wS1[NWTOT];

// ---------------- packed f32x2 helpers ----------------
__device__ __forceinline__ u64 ffma2(u64 a, u64 b, u64 c) {
    u64 d;
    asm("fma.rn.f32x2 %0, %1, %2, %3;" : "=l"(d) : "l"(a), "l"(b), "l"(c));
    return d;
}
__device__ __forceinline__ float2 unpack2(u64 v) {
    float2 r;
    asm("mov.b64 {%0, %1}, %2;" : "=f"(r.x), "=f"(r.y) : "l"(v));
    return r;
}
__device__ __forceinline__ u64 pack2(float lo, float hi) {
    u64 d;
    asm("mov.b64 %0, {%1, %2};" : "=l"(d) : "f"(lo), "f"(hi));
    return d;
}

// ---------------- K1: precompute cg, A, B ----------------
// JB=16 rows/block, x rows staged in smem, read back as float4 broadcasts.
__global__ void __launch_bounds__(128) precompute_kernel(
        const float* __restrict__ xg,
        const float* __restrict__ xm,
        const float* __restrict__ xj,
        const float* __restrict__ W0,
        const float* __restrict__ b0) {
    const int MB = (M_NODES + JB - 1) / JB;   // 63
    const int JBL = (J_NODES + JB - 1) / JB;  // 313
    int b = blockIdx.x;
    int t = threadIdx.x;
    __shared__ __align__(16) float xs[JB][H];

    if (b < MB + JBL) {
        const float* src; float* dst; int r0, cnt, woff;
        if (b < MB) { src = xm; dst = g_A; r0 = b * JB;        cnt = M_NODES; woff = 2 * H; }
        else        { src = xj; dst = g_B; r0 = (b - MB) * JB; cnt = J_NODES; woff = 3 * H; }
        #pragma unroll
        for (int jj = 0; jj < JB; jj++) {
            int r = r0 + jj; if (r >= cnt) r = cnt - 1;
            xs[jj][t] = src[r * H + t];
        }
        __syncthreads();
        float acc[JB];
        #pragma unroll
        for (int jj = 0; jj < JB; jj++) acc[jj] = 0.f;
        const float* w = W0 + woff * H + t;
        #pragma unroll 4
        for (int i4 = 0; i4 < H / 4; i4++) {
            float w0 = w[(4 * i4 + 0) * H];
            float w1 = w[(4 * i4 + 1) * H];
            float w2 = w[(4 * i4 + 2) * H];
            float w3 = w[(4 * i4 + 3) * H];
            #pragma unroll
            for (int jj = 0; jj < JB; jj++) {
                float4 x = *(const float4*)&xs[jj][4 * i4];
                acc[jj] += x.x * w0 + x.y * w1 + x.z * w2 + x.w * w3;
            }
        }
        #pragma unroll
        for (int jj = 0; jj < JB; jj++)
            if (r0 + jj < cnt) dst[(r0 + jj) * H + t] = acc[jj];
    } else {
        // graph constant: c = x_graph @ W0[0:2H] + b0
        __shared__ float x2[2 * H];
        x2[t] = xg[t];
        x2[t + H] = xg[t + H];
        __syncthreads();
        float acc = b0[t];
        const float* w = W0 + t;
        #pragma unroll 8
        for (int i = 0; i < 2 * H; i++) acc += x2[i] * w[i * H];
        g_c[t] = acc;
    }
}

// ---------------- K2: fused score + online softmax ----------------
// W1 pre-packed along the reduction dim in smem: W1p[i2][c] = (W1[2i2][c],
// W1[2i2+1][c]) as one u64. h staged as plain floats (natural (h2i,h2i+1)
// pairs). acc[r][c] holds (even-i, odd-i) partials; summed + bias at the end.
// 128KB smem -> 512 threads/block, 4 warps/SMSP.
__global__ void __launch_bounds__(512, 1) score_kernel(
        const int*   __restrict__ m_ids,
        const int*   __restrict__ job_idx,
        const float* __restrict__ W1,
        const float* __restrict__ b1,
        const float* __restrict__ W2,
        const float* __restrict__ b2) {
    extern __shared__ float smem[];
    u64*   W1p  = (u64*)smem;                       // [64][128] u64 = 64KB
    float* hstg = smem + 2 * 64 * H;                // 16 warps * RPW * H = 64KB

    int tid  = threadIdx.x;
    int lane = tid & 31;
    int wid  = tid >> 5;

    // pack W1 -> W1p
    for (int idx = tid; idx < 64 * H; idx += 512) {
        int i2 = idx >> 7, c = idx & (H - 1);
        W1p[idx] = pack2(W1[(2 * i2) * H + c], W1[(2 * i2 + 1) * H + c]);
    }

    float4 creg  = ((const float4*)g_c)[lane];
    float4 b1reg = ((const float4*)b1)[lane];
    float4 w2reg = ((const float4*)W2)[lane];
    float  b2v   = b2[0];
    __syncthreads();

    float* myh = hstg + wid * (RPW * H);
    const float4* A4 = (const float4*)g_A;
    const float4* B4 = (const float4*)g_B;

    float mx = -3.402823466e38f, Z = 0.f, S1 = 0.f;
    int   arg = 0x7fffffff;

    int gw = blockIdx.x * SWARPS + wid;
    const int stride = SBLOCKS * SWARPS * RPW;

    for (int base = gw * RPW; base + RPW <= NROWS; base += stride) {
        // ---- stage h0 = relu(c + A[m] + B[j]) for RPW rows ----
        #pragma unroll
        for (int r = 0; r < RPW; r++) {
            int m = m_ids[base + r];
            int j = job_idx[base + r];
            float4 a  = A4[m * (H / 4) + lane];
            float4 bb = B4[j * (H / 4) + lane];
            float4 h;
            h.x = fmaxf(creg.x + a.x + bb.x, 0.f);
            h.y = fmaxf(creg.y + a.y + bb.y, 0.f);
            h.z = fmaxf(creg.z + a.z + bb.z, 0.f);
            h.w = fmaxf(creg.w + a.w + bb.w, 0.f);
            ((float4*)(myh + r * H))[lane] = h;
        }
        __syncwarp();

        // ---- layer 2 on packed-reduction f32x2 ----
        u64 acc[RPW][4];
        #pragma unroll
        for (int r = 0; r < RPW; r++)
            acc[r][0] = acc[r][1] = acc[r][2] = acc[r][3] = 0ull;

        #pragma unroll 4
        for (int iq = 0; iq < H / 4; iq++) {          // i = 4*iq .. 4*iq+3
            const u64* wrowA = W1p + (2 * iq)     * H + 4 * lane;
            const u64* wrowB = W1p + (2 * iq + 1) * H + 4 * lane;
            ulonglong2 wA0 = *(const ulonglong2*)(wrowA);      // cols 4l,4l+1 (i pair A)
            ulonglong2 wA1 = *(const ulonglong2*)(wrowA + 2);  // cols 4l+2,4l+3
            ulonglong2 wB0 = *(const ulonglong2*)(wrowB);
            ulonglong2 wB1 = *(const ulonglong2*)(wrowB + 2);
            #pragma unroll
            for (int r = 0; r < RPW; r++) {
                ulonglong2 hp = *(const ulonglong2*)(myh + r * H + 4 * iq); // bcast
                acc[r][0] = ffma2(hp.x, wA0.x, acc[r][0]);
                acc[r][1] = ffma2(hp.x, wA0.y, acc[r][1]);
                acc[r][2] = ffma2(hp.x, wA1.x, acc[r][2]);
                acc[r][3] = ffma2(hp.x, wA1.y, acc[r][3]);
                acc[r][0] = ffma2(hp.y, wB0.x, acc[r][0]);
                acc[r][1] = ffma2(hp.y, wB0.y, acc[r][1]);
                acc[r][2] = ffma2(hp.y, wB1.x, acc[r][2]);
                acc[r][3] = ffma2(hp.y, wB1.y, acc[r][3]);
            }
        }

        // ---- layer 3 + warp reduce + online softmax ----
        #pragma unroll
        for (int r = 0; r < RPW; r++) {
            float2 p0 = unpack2(acc[r][0]);
            float2 p1 = unpack2(acc[r][1]);
            float2 p2 = unpack2(acc[r][2]);
            float2 p3 = unpack2(acc[r][3]);
            float h0 = p0.x + p0.y + b1reg.x;
            float h1 = p1.x + p1.y + b1reg.y;
            float h2 = p2.x + p2.y + b1reg.z;
            float h3 = p3.x + p3.y + b1reg.w;
            float s = fmaxf(h0, 0.f) * w2reg.x + fmaxf(h1, 0.f) * w2reg.y
                    + fmaxf(h2, 0.f) * w2reg.z + fmaxf(h3, 0.f) * w2reg.w;
            #pragma unroll
            for (int off = 16; off; off >>= 1)
                s += __shfl_xor_sync(0xffffffffu, s, off);
            s += b2v;
            if (s > mx) {
                float d = fmaxf(mx - s, -87.f);
                float e = expf(d);
                S1 = e * (S1 + d * Z);
                Z  = e * Z + 1.f;
                mx = s;
                arg = base + r;
            } else {
                float t = fmaxf(s - mx, -87.f);
                float e = expf(t);
                Z  += e;
                S1 += t * e;
            }
        }
        __syncwarp();
    }

    if (lane == 0) {
        g_wmax[gw] = mx;
        g_warg[gw] = arg;
        g_wZ[gw]   = Z;
        g_wS1[gw]  = S1;
    }
}

// ---------------- K3: merge warp partials, write outputs ----------------
__global__ void finalize_kernel(float* __restrict__ out) {
    __shared__ float smx[256], sZ[256], sS1[256];
    __shared__ int   sarg[256];
    int tid = threadIdx.x;

    float mx = -3.402823466e38f, Z = 0.f, S1 = 0.f;
    int   arg = 0x7fffffff;

    for (int i = tid; i < NWTOT; i += 256) {
        float qm = g_wmax[i], qZ = g_wZ[i], qS = g_wS1[i];
        int   qa = g_warg[i];
        if (qm > mx || (qm == mx && qa < arg)) {
            float d = fmaxf(mx - qm, -87.f);
            float e = expf(d);
            float Zo = Z, S1o = S1;
            Z  = qZ + e * Zo;
            S1 = qS + e * (S1o + d * Zo);
            mx = qm; arg = qa;
        } else {
            float d = fmaxf(qm - mx, -87.f);
            float e = expf(d);
            Z  += e * qZ;
            S1 += e * (qS + d * qZ);
        }
    }
    smx[tid] = mx; sarg[tid] = arg; sZ[tid] = Z; sS1[tid] = S1;
    __syncthreads();

    for (int s = 128; s; s >>= 1) {
        if (tid < s) {
            float qm = smx[tid + s], qZ = sZ[tid + s], qS = sS1[tid + s];
            int   qa = sarg[tid + s];
            if (qm > smx[tid] || (qm == smx[tid] && qa < sarg[tid])) {
                float d = fmaxf(smx[tid] - qm, -87.f);
                float e = expf(d);
                float Zo = sZ[tid], S1o = sS1[tid];
                sZ[tid]  = qZ + e * Zo;
                sS1[tid] = qS + e * (S1o + d * Zo);
                smx[tid] = qm; sarg[tid] = qa;
            } else {
                float d = fmaxf(qm - smx[tid], -87.f);
                float e = expf(d);
                sZ[tid]  += e * qZ;
                sS1[tid] += e * (qS + d * qZ);
            }
        }
        __syncthreads();
    }

    if (tid == 0) {
        float Zf   = sZ[0];
        float S1f  = sS1[0];
        float logZ = logf(Zf);
        out[0] = (float)sarg[0];
        out[1] = 1.0f / Zf;          // p[idx]
        out[2] = -logZ;              // logp[idx]
        out[3] = logZ - S1f / Zf;    // entropy
    }
}

// ---------------- launch ----------------
extern "C" void kernel_launch(void* const* d_in, const int* in_sizes, int n_in,
                              void* d_out, int out_size) {
    const float* x_graph = (const float*)d_in[0];
    const float* x_m     = (const float*)d_in[1];
    const float* x_job   = (const float*)d_in[2];
    const int*   m_ids   = (const int*)  d_in[3];
    const int*   job_idx = (const int*)  d_in[4];
    const float* W0      = (const float*)d_in[5];
    const float* b0      = (const float*)d_in[6];
    const float* W1      = (const float*)d_in[7];
    const float* b1      = (const float*)d_in[8];
    const float* W2      = (const float*)d_in[9];
    const float* b2      = (const float*)d_in[10];
    float* out = (float*)d_out;

    const int smem_bytes = 64 * H * 8 + SWARPS * RPW * H * 4;   // 64KB + 64KB
    cudaFuncSetAttribute(score_kernel,
                         cudaFuncAttributeMaxDynamicSharedMemorySize, smem_bytes);

    const int MB  = (M_NODES + JB - 1) / JB;
    const int JBL = (J_NODES + JB - 1) / JB;
    precompute_kernel<<<MB + JBL + 1, H>>>(x_graph, x_m, x_job, W0, b0);
    score_kernel<<<SBLOCKS, 512, smem_bytes>>>(m_ids, job_idx, W1, b1, W2, b2);
    finalize_kernel<<<1, 256>>>(out);
}